// round 1
// baseline (speedup 1.0000x reference)
#include <cuda_runtime.h>
#include <cuda_bf16.h>
#include <math.h>

// Problem constants
#define Bc 4
#define Sc 2048
#define Dc 512
#define Nc 16
#define DTR 32
#define BS (Bc*Sc)          // 8192 rows
#define BSD (BS*Dc)         // 4,194,304 elements

// ---- scratch (device globals; no allocation allowed) ----
__device__ float g_xn[BSD];
__device__ float g_z1[BSD];
__device__ float g_bwd[BSD];
__device__ float g_dbc[BS*64];
__device__ float g_p[BSD];    // exp(-delta)
__device__ float g_du[BSD];   // delta * u

// =====================================================================
// LayerNorm: one block per row (512 cols), 128 threads, float4
// =====================================================================
__global__ void ln_kernel(const float* __restrict__ x,
                          const float* __restrict__ gamma,
                          const float* __restrict__ beta,
                          float* __restrict__ xn)
{
    int row = blockIdx.x;
    int tid = threadIdx.x;     // 0..127
    const float4* xr = reinterpret_cast<const float4*>(x + (size_t)row * Dc);
    float4 v = xr[tid];
    float s = v.x + v.y + v.z + v.w;
    float q = v.x*v.x + v.y*v.y + v.z*v.z + v.w*v.w;
    #pragma unroll
    for (int o = 16; o; o >>= 1) {
        s += __shfl_xor_sync(0xffffffffu, s, o);
        q += __shfl_xor_sync(0xffffffffu, q, o);
    }
    __shared__ float ss[4], sq[4];
    if ((tid & 31) == 0) { ss[tid >> 5] = s; sq[tid >> 5] = q; }
    __syncthreads();
    s = ss[0] + ss[1] + ss[2] + ss[3];
    q = sq[0] + sq[1] + sq[2] + sq[3];
    float mean = s * (1.0f / Dc);
    float var  = q * (1.0f / Dc) - mean * mean;
    float rstd = rsqrtf(var + 1e-5f);
    float4 g  = reinterpret_cast<const float4*>(gamma)[tid];
    float4 bt = reinterpret_cast<const float4*>(beta)[tid];
    float4 o;
    o.x = (v.x - mean) * rstd * g.x + bt.x;
    o.y = (v.y - mean) * rstd * g.y + bt.y;
    o.z = (v.z - mean) * rstd * g.z + bt.z;
    o.w = (v.w - mean) * rstd * g.w + bt.w;
    reinterpret_cast<float4*>(xn + (size_t)row * Dc)[tid] = o;
}

// =====================================================================
// Tiled fp32 GEMM: C = A(MxK, lda) @ W(KxN, ldw) + bias
// BM=128, BN=64, BK=16, 256 threads, 8x4 per thread
// epi==0 : C0 = acc + bias
// epi==1 : raw = acc + bias; delta = softplus(raw);
//          C0 = exp(-delta); C1 = delta * aux   (fused delta epilogue)
// =====================================================================
#define GBM 128
#define GBN 64
#define GBK 16

__global__ __launch_bounds__(256)
void gemm_kernel(const float* __restrict__ A, int lda,
                 const float* __restrict__ W, int ldw,
                 const float* __restrict__ bias,
                 float* __restrict__ C0, float* __restrict__ C1,
                 const float* __restrict__ aux,
                 int M, int N, int K, int epi)
{
    __shared__ float sA[GBK][GBM + 4];
    __shared__ float sB[GBK][GBN];

    int tid = threadIdx.x;
    int bm = blockIdx.y * GBM;
    int bn = blockIdx.x * GBN;
    int ty = tid >> 4;     // 0..15 -> 8 rows each
    int tx = tid & 15;     // 0..15 -> 4 cols each

    float acc[8][4];
    #pragma unroll
    for (int i = 0; i < 8; i++)
        #pragma unroll
        for (int j = 0; j < 4; j++) acc[i][j] = 0.f;

    for (int k0 = 0; k0 < K; k0 += GBK) {
        // load A tile (128x16) as 512 float4, 2 per thread, store transposed
        #pragma unroll
        for (int r = 0; r < 2; r++) {
            int v = tid + r * 256;           // 0..511
            int m = v >> 2;                  // 0..127
            int kk = (v & 3) << 2;           // 0,4,8,12
            float4 a4 = *reinterpret_cast<const float4*>(
                A + (size_t)(bm + m) * lda + k0 + kk);
            sA[kk + 0][m] = a4.x;
            sA[kk + 1][m] = a4.y;
            sA[kk + 2][m] = a4.z;
            sA[kk + 3][m] = a4.w;
        }
        // load B tile (16x64) as 256 float4, 1 per thread
        {
            int k = tid >> 4;                // 0..15
            int nn = (tid & 15) << 2;        // 0..60
            float4 b4 = *reinterpret_cast<const float4*>(
                W + (size_t)(k0 + k) * ldw + bn + nn);
            *reinterpret_cast<float4*>(&sB[k][nn]) = b4;
        }
        __syncthreads();

        #pragma unroll
        for (int k = 0; k < GBK; k++) {
            float4 a0 = *reinterpret_cast<const float4*>(&sA[k][ty * 8]);
            float4 a1 = *reinterpret_cast<const float4*>(&sA[k][ty * 8 + 4]);
            float4 b0 = *reinterpret_cast<const float4*>(&sB[k][tx * 4]);
            float a[8] = {a0.x, a0.y, a0.z, a0.w, a1.x, a1.y, a1.z, a1.w};
            float bb[4] = {b0.x, b0.y, b0.z, b0.w};
            #pragma unroll
            for (int i = 0; i < 8; i++)
                #pragma unroll
                for (int j = 0; j < 4; j++)
                    acc[i][j] = fmaf(a[i], bb[j], acc[i][j]);
        }
        __syncthreads();
    }

    float bv[4];
    #pragma unroll
    for (int j = 0; j < 4; j++)
        bv[j] = bias ? __ldg(bias + bn + tx * 4 + j) : 0.f;

    #pragma unroll
    for (int i = 0; i < 8; i++) {
        int m = bm + ty * 8 + i;
        #pragma unroll
        for (int j = 0; j < 4; j++) {
            int nidx = bn + tx * 4 + j;
            float v = acc[i][j] + bv[j];
            size_t idx = (size_t)m * N + nidx;
            if (epi == 0) {
                C0[idx] = v;
            } else {
                // softplus (stable)
                float dlt = (v > 20.f) ? v : log1pf(__expf(v));
                C0[idx] = __expf(-dlt);            // p
                C1[idx] = dlt * __ldg(aux + idx);  // delta * u
            }
        }
    }
}

// =====================================================================
// SSM scan, one thread per (b,d,n). 16-lane groups share d.
// Exploits A[d,n] = -(n+1) (verified at runtime): deltaA = p^(n+1).
// Fuses final elementwise: out = (z1 + x2)*silu(z1) + x
// =====================================================================
__global__ __launch_bounds__(128)
void ssm_scan_kernel(const float* __restrict__ p,
                     const float* __restrict__ du,
                     const float* __restrict__ dbc,
                     const float* __restrict__ u,
                     const float* __restrict__ z1,
                     const float* __restrict__ x,
                     const float* __restrict__ A_log,
                     const float* __restrict__ D_ssm,
                     float* __restrict__ out)
{
    int t = blockIdx.x * blockDim.x + threadIdx.x;  // 0..32767
    int n = t & (Nc - 1);
    int d = (t >> 4) & (Dc - 1);
    int b = t >> 13;

    float af = __expf(__ldg(A_log + d * Nc + n));   // -A[d,n]
    int ai = (int)rintf(af);
    bool exact = (fabsf(af - (float)ai) < 1e-4f * af) && (ai >= 1) && (ai <= 32);
    float Dd = __ldg(D_ssm + d);

    float h = 0.f;
    int base  = (b * Sc) * Dc + d;
    int bbase = (b * Sc) * 64;

    #pragma unroll 2
    for (int s = 0; s < Sc; ++s) {
        float pv  = __ldg(p  + base);
        float duv = __ldg(du + base);
        float Bv  = __ldg(dbc + bbase + DTR + n);
        float Cv  = __ldg(dbc + bbase + DTR + Nc + n);

        float dA;
        if (exact) {
            float pw = pv;
            float r = (ai & 1) ? pw : 1.f;
            pw *= pw; if (ai & 2)  r *= pw;
            pw *= pw; if (ai & 4)  r *= pw;
            pw *= pw; if (ai & 8)  r *= pw;
            pw *= pw; if (ai & 16) r *= pw;
            pw *= pw; if (ai & 32) r *= pw;
            dA = r;
        } else {
            dA = __powf(pv, af);   // p^(-A) == exp(delta*A)
        }

        h = fmaf(dA, h, duv * Bv);
        float part = h * Cv;
        part += __shfl_xor_sync(0xffffffffu, part, 8, 16);
        part += __shfl_xor_sync(0xffffffffu, part, 4, 16);
        part += __shfl_xor_sync(0xffffffffu, part, 2, 16);
        part += __shfl_xor_sync(0xffffffffu, part, 1, 16);

        if (n == 0) {
            float uv  = __ldg(u  + base);
            float zv  = __ldg(z1 + base);
            float xv  = __ldg(x  + base);
            float x2v = part + Dd * uv;
            float sil = zv / (1.f + __expf(-zv));   // silu(z1)
            out[base] = (zv + x2v) * sil + xv;
        }
        base  += Dc;
        bbase += 64;
    }
}

// =====================================================================
// launch
// =====================================================================
extern "C" void kernel_launch(void* const* d_in, const int* in_sizes, int n_in,
                              void* d_out, int out_size)
{
    const float* x      = (const float*)d_in[0];
    const float* gamma  = (const float*)d_in[1];
    const float* beta   = (const float*)d_in[2];
    const float* W_proj = (const float*)d_in[3];
    const float* b_proj = (const float*)d_in[4];
    // d_in[5] W_fwd, d_in[6] b_fwd: dead code in the reference (x1_ssm unused)
    const float* W_bwd  = (const float*)d_in[7];
    const float* b_bwd  = (const float*)d_in[8];
    const float* W_dbc  = (const float*)d_in[9];
    const float* W_dt   = (const float*)d_in[10];
    const float* b_dt   = (const float*)d_in[11];
    const float* A_log  = (const float*)d_in[12];
    const float* D_ssm  = (const float*)d_in[13];
    float* out = (float*)d_out;

    static float *p_xn = nullptr, *p_z1, *p_bwd, *p_dbc, *p_p, *p_du;
    if (!p_xn) {
        void* v;
        cudaGetSymbolAddress(&v, g_xn);  p_xn  = (float*)v;
        cudaGetSymbolAddress(&v, g_z1);  p_z1  = (float*)v;
        cudaGetSymbolAddress(&v, g_bwd); p_bwd = (float*)v;
        cudaGetSymbolAddress(&v, g_dbc); p_dbc = (float*)v;
        cudaGetSymbolAddress(&v, g_p);   p_p   = (float*)v;
        cudaGetSymbolAddress(&v, g_du);  p_du  = (float*)v;
    }

    // 1) LayerNorm
    ln_kernel<<<BS, 128>>>(x, gamma, beta, p_xn);

    // 2) z1 = xn @ W_proj + b_proj   (8192 x 512 x 512)
    dim3 gBig(Dc / GBN, BS / GBM);
    gemm_kernel<<<gBig, 256>>>(p_xn, Dc, W_proj, Dc, b_proj,
                               p_z1, nullptr, nullptr, BS, Dc, Dc, 0);

    // 3) bwd = z1 @ W_bwd + b_bwd
    gemm_kernel<<<gBig, 256>>>(p_z1, Dc, W_bwd, Dc, b_bwd,
                               p_bwd, nullptr, nullptr, BS, Dc, Dc, 0);

    // 4) dbc = bwd @ W_dbc           (8192 x 64 x 512, no bias)
    dim3 gDbc(64 / GBN, BS / GBM);
    gemm_kernel<<<gDbc, 256>>>(p_bwd, Dc, W_dbc, 64, nullptr,
                               p_dbc, nullptr, nullptr, BS, 64, Dc, 0);

    // 5) delta GEMM + fused softplus/exp epilogue -> p, du
    //    raw = dbc[:, :32] @ W_dt + b_dt   (8192 x 512 x 32, lda=64)
    dim3 gDt(Dc / GBN, BS / GBM);
    gemm_kernel<<<gDt, 256>>>(p_dbc, 64, W_dt, Dc, b_dt,
                              p_p, p_du, p_bwd, BS, Dc, DTR, 1);

    // 6) SSM scan + fused final elementwise -> out
    ssm_scan_kernel<<<(Bc * Dc * Nc) / 128, 128>>>(
        p_p, p_du, p_dbc, p_bwd, p_z1, x, A_log, D_ssm, out);
}

// round 2
// speedup vs baseline: 3.0143x; 3.0143x over previous
#include <cuda_runtime.h>
#include <cuda_bf16.h>
#include <math.h>

// Problem constants
#define Bc 4
#define Sc 2048
#define Dc 512
#define Nc 16
#define DTR 32
#define BS (Bc*Sc)          // 8192 rows
#define BSD (BS*Dc)         // 4,194,304 elements
#define CL 128              // scan chunk length
#define NCH (Sc/CL)         // 16 chunks
#define NSCAN (Bc*NCH*Dc*Nc)  // 524288 scan threads

// ---- scratch (device globals; no allocation allowed) ----
__device__ float g_xn[BSD];
__device__ float g_z1[BSD];
__device__ float g_bwd[BSD];
__device__ float g_dbc[BS*64];
__device__ float g_p[BSD];      // exp(-delta)
__device__ float g_du[BSD];     // delta * u
__device__ float g_afin[NSCAN]; // per-chunk prod(a)
__device__ float g_hfin[NSCAN]; // per-chunk local final h
__device__ float g_h0[NSCAN];   // per-chunk entrance h

// =====================================================================
// LayerNorm: one block per row (512 cols), 128 threads, float4
// =====================================================================
__global__ void ln_kernel(const float* __restrict__ x,
                          const float* __restrict__ gamma,
                          const float* __restrict__ beta,
                          float* __restrict__ xn)
{
    int row = blockIdx.x;
    int tid = threadIdx.x;
    const float4* xr = reinterpret_cast<const float4*>(x + (size_t)row * Dc);
    float4 v = xr[tid];
    float s = v.x + v.y + v.z + v.w;
    float q = v.x*v.x + v.y*v.y + v.z*v.z + v.w*v.w;
    #pragma unroll
    for (int o = 16; o; o >>= 1) {
        s += __shfl_xor_sync(0xffffffffu, s, o);
        q += __shfl_xor_sync(0xffffffffu, q, o);
    }
    __shared__ float ss[4], sq[4];
    if ((tid & 31) == 0) { ss[tid >> 5] = s; sq[tid >> 5] = q; }
    __syncthreads();
    s = ss[0] + ss[1] + ss[2] + ss[3];
    q = sq[0] + sq[1] + sq[2] + sq[3];
    float mean = s * (1.0f / Dc);
    float var  = q * (1.0f / Dc) - mean * mean;
    float rstd = rsqrtf(var + 1e-5f);
    float4 g  = reinterpret_cast<const float4*>(gamma)[tid];
    float4 bt = reinterpret_cast<const float4*>(beta)[tid];
    float4 o;
    o.x = (v.x - mean) * rstd * g.x + bt.x;
    o.y = (v.y - mean) * rstd * g.y + bt.y;
    o.z = (v.z - mean) * rstd * g.z + bt.z;
    o.w = (v.w - mean) * rstd * g.w + bt.w;
    reinterpret_cast<float4*>(xn + (size_t)row * Dc)[tid] = o;
}

// =====================================================================
// 128x128x16 double-buffered fp32 GEMM, 256 threads, 8x8 per thread
// epi==0 : C0 = acc + bias
// epi==1 : raw = acc + bias; delta = softplus(raw);
//          C0 = exp(-delta); C1 = delta * aux
// =====================================================================
__global__ __launch_bounds__(256)
void gemm128_kernel(const float* __restrict__ A, int lda,
                    const float* __restrict__ W, int ldw,
                    const float* __restrict__ bias,
                    float* __restrict__ C0, float* __restrict__ C1,
                    const float* __restrict__ aux,
                    int M, int N, int K, int epi)
{
    __shared__ __align__(16) float sA[2][16][132];
    __shared__ __align__(16) float sB[2][16][128];

    int tid = threadIdx.x;
    int bm = blockIdx.y * 128;
    int bn = blockIdx.x * 128;
    int tr = tid >> 4;        // 0..15
    int tc = tid & 15;        // 0..15

    float acc[8][8];
    #pragma unroll
    for (int i = 0; i < 8; i++)
        #pragma unroll
        for (int j = 0; j < 8; j++) acc[i][j] = 0.f;

    // ---- prologue: load tile k0=0 into buffer 0 ----
    #pragma unroll
    for (int r = 0; r < 2; r++) {
        int v = tid + r * 256;
        int m = v >> 2, kk = (v & 3) << 2;
        float4 a4 = *reinterpret_cast<const float4*>(A + (size_t)(bm + m) * lda + kk);
        sA[0][kk+0][m] = a4.x; sA[0][kk+1][m] = a4.y;
        sA[0][kk+2][m] = a4.z; sA[0][kk+3][m] = a4.w;
    }
    #pragma unroll
    for (int r = 0; r < 2; r++) {
        int v = tid + r * 256;
        int k = v >> 5, nn = (v & 31) << 2;
        float4 b4 = *reinterpret_cast<const float4*>(W + (size_t)k * ldw + bn + nn);
        *reinterpret_cast<float4*>(&sB[0][k][nn]) = b4;
    }
    __syncthreads();

    int buf = 0;
    for (int k0 = 0; k0 < K; k0 += 16) {
        int nxt = k0 + 16;
        if (nxt < K) {
            int nb = buf ^ 1;
            #pragma unroll
            for (int r = 0; r < 2; r++) {
                int v = tid + r * 256;
                int m = v >> 2, kk = (v & 3) << 2;
                float4 a4 = *reinterpret_cast<const float4*>(
                    A + (size_t)(bm + m) * lda + nxt + kk);
                sA[nb][kk+0][m] = a4.x; sA[nb][kk+1][m] = a4.y;
                sA[nb][kk+2][m] = a4.z; sA[nb][kk+3][m] = a4.w;
            }
            #pragma unroll
            for (int r = 0; r < 2; r++) {
                int v = tid + r * 256;
                int k = v >> 5, nn = (v & 31) << 2;
                float4 b4 = *reinterpret_cast<const float4*>(
                    W + (size_t)(nxt + k) * ldw + bn + nn);
                *reinterpret_cast<float4*>(&sB[nb][k][nn]) = b4;
            }
        }
        #pragma unroll
        for (int k = 0; k < 16; k++) {
            float a[8], bb[8];
            *reinterpret_cast<float4*>(&a[0]) =
                *reinterpret_cast<const float4*>(&sA[buf][k][tr * 4]);
            *reinterpret_cast<float4*>(&a[4]) =
                *reinterpret_cast<const float4*>(&sA[buf][k][tr * 4 + 64]);
            *reinterpret_cast<float4*>(&bb[0]) =
                *reinterpret_cast<const float4*>(&sB[buf][k][tc * 4]);
            *reinterpret_cast<float4*>(&bb[4]) =
                *reinterpret_cast<const float4*>(&sB[buf][k][tc * 4 + 64]);
            #pragma unroll
            for (int i = 0; i < 8; i++)
                #pragma unroll
                for (int j = 0; j < 8; j++)
                    acc[i][j] = fmaf(a[i], bb[j], acc[i][j]);
        }
        __syncthreads();
        buf ^= 1;
    }

    float bv[8];
    #pragma unroll
    for (int j = 0; j < 8; j++) {
        int nidx = bn + (j < 4 ? tc * 4 + j : tc * 4 + 60 + j);
        bv[j] = bias ? __ldg(bias + nidx) : 0.f;
    }

    #pragma unroll
    for (int i = 0; i < 8; i++) {
        int m = bm + (i < 4 ? tr * 4 + i : tr * 4 + 60 + i);
        #pragma unroll
        for (int j = 0; j < 8; j++) {
            int nidx = bn + (j < 4 ? tc * 4 + j : tc * 4 + 60 + j);
            float v = acc[i][j] + bv[j];
            size_t idx = (size_t)m * N + nidx;
            if (epi == 0) {
                C0[idx] = v;
            } else {
                float dlt = (v > 20.f) ? v : log1pf(__expf(v));
                C0[idx] = __expf(-dlt);
                C1[idx] = dlt * __ldg(aux + idx);
            }
        }
    }
}

// ===== old 128x64 GEMM kept for the N=64 dbc GEMM =====
#define GBM 128
#define GBN 64
#define GBK 16
__global__ __launch_bounds__(256)
void gemm_kernel(const float* __restrict__ A, int lda,
                 const float* __restrict__ W, int ldw,
                 const float* __restrict__ bias,
                 float* __restrict__ C0,
                 int M, int N, int K)
{
    __shared__ float sA[GBK][GBM + 4];
    __shared__ float sB[GBK][GBN];
    int tid = threadIdx.x;
    int bm = blockIdx.y * GBM;
    int bn = blockIdx.x * GBN;
    int ty = tid >> 4, tx = tid & 15;
    float acc[8][4];
    #pragma unroll
    for (int i = 0; i < 8; i++)
        #pragma unroll
        for (int j = 0; j < 4; j++) acc[i][j] = 0.f;

    for (int k0 = 0; k0 < K; k0 += GBK) {
        #pragma unroll
        for (int r = 0; r < 2; r++) {
            int v = tid + r * 256;
            int m = v >> 2, kk = (v & 3) << 2;
            float4 a4 = *reinterpret_cast<const float4*>(
                A + (size_t)(bm + m) * lda + k0 + kk);
            sA[kk+0][m] = a4.x; sA[kk+1][m] = a4.y;
            sA[kk+2][m] = a4.z; sA[kk+3][m] = a4.w;
        }
        {
            int k = tid >> 4, nn = (tid & 15) << 2;
            float4 b4 = *reinterpret_cast<const float4*>(
                W + (size_t)(k0 + k) * ldw + bn + nn);
            *reinterpret_cast<float4*>(&sB[k][nn]) = b4;
        }
        __syncthreads();
        #pragma unroll
        for (int k = 0; k < GBK; k++) {
            float4 a0 = *reinterpret_cast<const float4*>(&sA[k][ty * 8]);
            float4 a1 = *reinterpret_cast<const float4*>(&sA[k][ty * 8 + 4]);
            float4 b0 = *reinterpret_cast<const float4*>(&sB[k][tx * 4]);
            float a[8] = {a0.x, a0.y, a0.z, a0.w, a1.x, a1.y, a1.z, a1.w};
            float bb[4] = {b0.x, b0.y, b0.z, b0.w};
            #pragma unroll
            for (int i = 0; i < 8; i++)
                #pragma unroll
                for (int j = 0; j < 4; j++)
                    acc[i][j] = fmaf(a[i], bb[j], acc[i][j]);
        }
        __syncthreads();
    }
    #pragma unroll
    for (int i = 0; i < 8; i++) {
        int m = bm + ty * 8 + i;
        #pragma unroll
        for (int j = 0; j < 4; j++) {
            int nidx = bn + tx * 4 + j;
            float v = acc[i][j] + (bias ? __ldg(bias + nidx) : 0.f);
            C0[(size_t)m * N + nidx] = v;
        }
    }
}

// =====================================================================
// Chunked SSM scan: a[s] = p[s,d]^(n+1) exact-power trick,
// thread t = ((b*NCH+ch)*Dc + d)*16 + n  -> lanes 0-15 share (b,ch,d)
// =====================================================================
__device__ __forceinline__ float pow_dA(float pv, bool exact, int ai, float af)
{
    if (exact) {
        float pw = pv;
        float r = (ai & 1) ? pw : 1.f;
        pw *= pw; if (ai & 2)  r *= pw;
        pw *= pw; if (ai & 4)  r *= pw;
        pw *= pw; if (ai & 8)  r *= pw;
        pw *= pw; if (ai & 16) r *= pw;
        pw *= pw; if (ai & 32) r *= pw;
        return r;
    }
    return __powf(pv, af);
}

__global__ __launch_bounds__(256)
void scan_passA(const float* __restrict__ p,
                const float* __restrict__ du,
                const float* __restrict__ dbc,
                const float* __restrict__ A_log,
                float* __restrict__ afin,
                float* __restrict__ hfin)
{
    int t = blockIdx.x * blockDim.x + threadIdx.x;
    int n = t & 15;
    int d = (t >> 4) & (Dc - 1);
    int ch = (t >> 13) & (NCH - 1);
    int b = t >> 17;

    float af = __expf(__ldg(A_log + d * Nc + n));
    int ai = (int)rintf(af);
    bool exact = (fabsf(af - (float)ai) < 1e-4f * af) && (ai >= 1) && (ai <= 32);

    float aprod = 1.f, h = 0.f;
    int base  = (b * Sc + ch * CL) * Dc + d;
    int bbase = (b * Sc + ch * CL) * 64;
    #pragma unroll 4
    for (int s = 0; s < CL; ++s) {
        float pv  = __ldg(p + base);
        float duv = __ldg(du + base);
        float Bv  = __ldg(dbc + bbase + DTR + n);
        float dA  = pow_dA(pv, exact, ai, af);
        aprod *= dA;
        h = fmaf(dA, h, duv * Bv);
        base += Dc; bbase += 64;
    }
    afin[t] = aprod;
    hfin[t] = h;
}

__global__ __launch_bounds__(256)
void scan_mid(const float* __restrict__ afin,
              const float* __restrict__ hfin,
              float* __restrict__ h0)
{
    int t = blockIdx.x * blockDim.x + threadIdx.x;  // 0..32767: (b,d,n)
    int dn = t & (Dc * 16 - 1);
    int b  = t >> 13;
    float run = 0.f;
    #pragma unroll
    for (int ch = 0; ch < NCH; ++ch) {
        int tt = ((b * NCH + ch) * Dc * 16) + dn;
        h0[tt] = run;
        run = fmaf(__ldg(afin + tt), run, __ldg(hfin + tt));
    }
}

__global__ __launch_bounds__(256)
void scan_passB(const float* __restrict__ p,
                const float* __restrict__ du,
                const float* __restrict__ dbc,
                const float* __restrict__ h0,
                const float* __restrict__ u,
                const float* __restrict__ z1,
                const float* __restrict__ x,
                const float* __restrict__ A_log,
                const float* __restrict__ D_ssm,
                float* __restrict__ out)
{
    int t = blockIdx.x * blockDim.x + threadIdx.x;
    int n = t & 15;
    int d = (t >> 4) & (Dc - 1);
    int ch = (t >> 13) & (NCH - 1);
    int b = t >> 17;

    float af = __expf(__ldg(A_log + d * Nc + n));
    int ai = (int)rintf(af);
    bool exact = (fabsf(af - (float)ai) < 1e-4f * af) && (ai >= 1) && (ai <= 32);
    float Dd = __ldg(D_ssm + d);

    float h = h0[t];
    int base  = (b * Sc + ch * CL) * Dc + d;
    int bbase = (b * Sc + ch * CL) * 64;
    #pragma unroll 2
    for (int s = 0; s < CL; ++s) {
        float pv  = __ldg(p + base);
        float duv = __ldg(du + base);
        float Bv  = __ldg(dbc + bbase + DTR + n);
        float Cv  = __ldg(dbc + bbase + DTR + Nc + n);
        float dA  = pow_dA(pv, exact, ai, af);
        h = fmaf(dA, h, duv * Bv);
        float part = h * Cv;
        part += __shfl_xor_sync(0xffffffffu, part, 8, 16);
        part += __shfl_xor_sync(0xffffffffu, part, 4, 16);
        part += __shfl_xor_sync(0xffffffffu, part, 2, 16);
        part += __shfl_xor_sync(0xffffffffu, part, 1, 16);
        if (n == 0) {
            float uv  = __ldg(u + base);
            float zv  = __ldg(z1 + base);
            float xv  = __ldg(x + base);
            float x2v = part + Dd * uv;
            float sil = zv / (1.f + __expf(-zv));
            out[base] = (zv + x2v) * sil + xv;
        }
        base += Dc; bbase += 64;
    }
}

// =====================================================================
// launch
// =====================================================================
extern "C" void kernel_launch(void* const* d_in, const int* in_sizes, int n_in,
                              void* d_out, int out_size)
{
    const float* x      = (const float*)d_in[0];
    const float* gamma  = (const float*)d_in[1];
    const float* beta   = (const float*)d_in[2];
    const float* W_proj = (const float*)d_in[3];
    const float* b_proj = (const float*)d_in[4];
    // d_in[5] W_fwd, d_in[6] b_fwd: dead code (x1_ssm unused in reference)
    const float* W_bwd  = (const float*)d_in[7];
    const float* b_bwd  = (const float*)d_in[8];
    const float* W_dbc  = (const float*)d_in[9];
    const float* W_dt   = (const float*)d_in[10];
    const float* b_dt   = (const float*)d_in[11];
    const float* A_log  = (const float*)d_in[12];
    const float* D_ssm  = (const float*)d_in[13];
    float* out = (float*)d_out;

    static float *p_xn = nullptr, *p_z1, *p_bwd, *p_dbc, *p_p, *p_du,
                 *p_afin, *p_hfin, *p_h0;
    if (!p_xn) {
        void* v;
        cudaGetSymbolAddress(&v, g_xn);   p_xn   = (float*)v;
        cudaGetSymbolAddress(&v, g_z1);   p_z1   = (float*)v;
        cudaGetSymbolAddress(&v, g_bwd);  p_bwd  = (float*)v;
        cudaGetSymbolAddress(&v, g_dbc);  p_dbc  = (float*)v;
        cudaGetSymbolAddress(&v, g_p);    p_p    = (float*)v;
        cudaGetSymbolAddress(&v, g_du);   p_du   = (float*)v;
        cudaGetSymbolAddress(&v, g_afin); p_afin = (float*)v;
        cudaGetSymbolAddress(&v, g_hfin); p_hfin = (float*)v;
        cudaGetSymbolAddress(&v, g_h0);   p_h0   = (float*)v;
    }

    // 1) LayerNorm
    ln_kernel<<<BS, 128>>>(x, gamma, beta, p_xn);

    // 2) z1 = xn @ W_proj + b_proj   (8192 x 512 x 512)
    dim3 gBig(Dc / 128, BS / 128);
    gemm128_kernel<<<gBig, 256>>>(p_xn, Dc, W_proj, Dc, b_proj,
                                  p_z1, nullptr, nullptr, BS, Dc, Dc, 0);

    // 3) bwd = z1 @ W_bwd + b_bwd
    gemm128_kernel<<<gBig, 256>>>(p_z1, Dc, W_bwd, Dc, b_bwd,
                                  p_bwd, nullptr, nullptr, BS, Dc, Dc, 0);

    // 4) dbc = bwd @ W_dbc           (8192 x 64 x 512)
    dim3 gDbc(64 / GBN, BS / GBM);
    gemm_kernel<<<gDbc, 256>>>(p_bwd, Dc, W_dbc, 64, nullptr,
                               p_dbc, BS, 64, Dc);

    // 5) delta GEMM + fused softplus/exp epilogue -> p, du
    dim3 gDt(Dc / 128, BS / 128);
    gemm128_kernel<<<gDt, 256>>>(p_dbc, 64, W_dt, Dc, b_dt,
                                 p_p, p_du, p_bwd, BS, Dc, DTR, 1);

    // 6) chunk-parallel SSM scan + fused final elementwise
    scan_passA<<<NSCAN / 256, 256>>>(p_p, p_du, p_dbc, A_log, p_afin, p_hfin);
    scan_mid<<<(Bc * Dc * Nc) / 256, 256>>>(p_afin, p_hfin, p_h0);
    scan_passB<<<NSCAN / 256, 256>>>(p_p, p_du, p_dbc, p_h0,
                                     p_bwd, p_z1, x, A_log, D_ssm, out);
}

// round 3
// speedup vs baseline: 3.3750x; 1.1197x over previous
#include <cuda_runtime.h>
#include <cuda_bf16.h>
#include <math.h>
#include <stdint.h>

// Problem constants
#define Bc 4
#define Sc 2048
#define Dc 512
#define Nc 16
#define DTR 32
#define BS (Bc*Sc)          // 8192 rows
#define BSD (BS*Dc)         // 4,194,304 elements
#define CL 128              // scan chunk length
#define NCH (Sc/CL)         // 16 chunks
#define NSCAN (Bc*NCH*Dc*Nc)  // 524288 scan threads

// ---- scratch (device globals; no allocation allowed) ----
__device__ float g_xn[BSD];
__device__ float g_z1[BSD];
__device__ float g_bwd[BSD];
__device__ float g_dbc[BS*64];
__device__ float g_p[BSD];      // exp(-delta)
__device__ float g_du[BSD];     // delta * u
__device__ float g_afin[NSCAN];
__device__ float g_hfin[NSCAN];
__device__ float g_h0[NSCAN];

// =====================================================================
// LayerNorm
// =====================================================================
__global__ void ln_kernel(const float* __restrict__ x,
                          const float* __restrict__ gamma,
                          const float* __restrict__ beta,
                          float* __restrict__ xn)
{
    int row = blockIdx.x;
    int tid = threadIdx.x;
    const float4* xr = reinterpret_cast<const float4*>(x + (size_t)row * Dc);
    float4 v = xr[tid];
    float s = v.x + v.y + v.z + v.w;
    float q = v.x*v.x + v.y*v.y + v.z*v.z + v.w*v.w;
    #pragma unroll
    for (int o = 16; o; o >>= 1) {
        s += __shfl_xor_sync(0xffffffffu, s, o);
        q += __shfl_xor_sync(0xffffffffu, q, o);
    }
    __shared__ float ss[4], sq[4];
    if ((tid & 31) == 0) { ss[tid >> 5] = s; sq[tid >> 5] = q; }
    __syncthreads();
    s = ss[0] + ss[1] + ss[2] + ss[3];
    q = sq[0] + sq[1] + sq[2] + sq[3];
    float mean = s * (1.0f / Dc);
    float var  = q * (1.0f / Dc) - mean * mean;
    float rstd = rsqrtf(var + 1e-5f);
    float4 g  = reinterpret_cast<const float4*>(gamma)[tid];
    float4 bt = reinterpret_cast<const float4*>(beta)[tid];
    float4 o;
    o.x = (v.x - mean) * rstd * g.x + bt.x;
    o.y = (v.y - mean) * rstd * g.y + bt.y;
    o.z = (v.z - mean) * rstd * g.z + bt.z;
    o.w = (v.w - mean) * rstd * g.w + bt.w;
    reinterpret_cast<float4*>(xn + (size_t)row * Dc)[tid] = o;
}

// =====================================================================
// Split-bf16 tensor-core GEMM (3x mma error-compensated, ~fp32 accuracy)
// C = A(MxK, lda) @ W(KxN, ldw) + bias
// epi==0: C0 = v
// epi==1: p = 1/(1+e^v) -> C0 ; delta = softplus(v); C1 = delta*aux
// =====================================================================
__device__ __forceinline__ void mma16816(float* c, const uint32_t* a, const uint32_t* b)
{
    asm volatile(
        "mma.sync.aligned.m16n8k16.row.col.f32.bf16.bf16.f32 "
        "{%0,%1,%2,%3}, {%4,%5,%6,%7}, {%8,%9}, {%0,%1,%2,%3};\n"
        : "+f"(c[0]), "+f"(c[1]), "+f"(c[2]), "+f"(c[3])
        : "r"(a[0]), "r"(a[1]), "r"(a[2]), "r"(a[3]),
          "r"(b[0]), "r"(b[1]));
}

__device__ __forceinline__ uint32_t pack2(float x, float y)
{
    __nv_bfloat16 hx = __float2bfloat16(x);
    __nv_bfloat16 hy = __float2bfloat16(y);
    uint32_t ux = (uint32_t)__bfloat16_as_ushort(hx);
    uint32_t uy = (uint32_t)__bfloat16_as_ushort(hy);
    return ux | (uy << 16);
}
__device__ __forceinline__ void split2(float x, float y, uint32_t& hi, uint32_t& lo)
{
    __nv_bfloat16 hx = __float2bfloat16(x);
    __nv_bfloat16 hy = __float2bfloat16(y);
    float rx = x - __bfloat162float(hx);
    float ry = y - __bfloat162float(hy);
    uint32_t uhx = (uint32_t)__bfloat16_as_ushort(hx);
    uint32_t uhy = (uint32_t)__bfloat16_as_ushort(hy);
    hi = uhx | (uhy << 16);
    lo = ((uint32_t)__bfloat16_as_ushort(__float2bfloat16(rx))) |
         (((uint32_t)__bfloat16_as_ushort(__float2bfloat16(ry))) << 16);
}

__device__ __forceinline__ void dt_epilogue(float v, size_t idx,
                                            float* C0, float* C1,
                                            const float* aux)
{
    float p, dlt;
    if (v > 15.f) {
        p = __expf(-v);
        dlt = v;
    } else {
        float ev = __expf(v);
        p = __fdividef(1.f, 1.f + ev);
        dlt = __logf(1.f + ev);
    }
    C0[idx] = p;
    C1[idx] = dlt * __ldg(aux + idx);
}

// BM x BN block tile, BK=16. WMT/WNT = per-warp 16x8 tile counts.
template<int BM, int BN, int WMT, int WNT, int NTHR>
__global__ __launch_bounds__(NTHR)
void mma_gemm(const float* __restrict__ A, int lda,
              const float* __restrict__ W, int ldw,
              const float* __restrict__ bias,
              float* __restrict__ C0, float* __restrict__ C1,
              const float* __restrict__ aux,
              int M, int N, int K, int epi)
{
    constexpr int WARPS_N = BN / (WNT * 8);
    constexpr int RS = 9;  // row stride in uint32 (8 pairs + 1 pad)

    // [buf][hi/lo][row][RS] in uint32 units
    __shared__ uint32_t sA[2][2][BM * RS];
    __shared__ uint32_t sB[2][2][BN * RS];

    int tid = threadIdx.x;
    int bm = blockIdx.y * BM;
    int bn = blockIdx.x * BN;
    int wid = tid >> 5, l = tid & 31;
    int wn = wid % WARPS_N, wm = wid / WARPS_N;
    int m_off = wm * (WMT * 16);
    int n_off = wn * (WNT * 8);

    float acc[WMT][WNT][4];
    #pragma unroll
    for (int i = 0; i < WMT; i++)
        #pragma unroll
        for (int j = 0; j < WNT; j++)
            #pragma unroll
            for (int c = 0; c < 4; c++) acc[i][j][c] = 0.f;

    constexpr int A_LD = (BM * 4) / NTHR;   // float4 per thread
    constexpr int B_LD = (BN * 4) / NTHR;

    // ---- tile loader ----
    auto load_tile = [&](int k0, int buf) {
        #pragma unroll
        for (int r = 0; r < A_LD; r++) {
            int v = tid + r * NTHR;
            int m = v >> 2, kq = v & 3;
            float4 a4 = *reinterpret_cast<const float4*>(
                A + (size_t)(bm + m) * lda + k0 + 4 * kq);
            uint32_t h0, l0, h1, l1;
            split2(a4.x, a4.y, h0, l0);
            split2(a4.z, a4.w, h1, l1);
            sA[buf][0][m * RS + 2 * kq]     = h0;
            sA[buf][0][m * RS + 2 * kq + 1] = h1;
            sA[buf][1][m * RS + 2 * kq]     = l0;
            sA[buf][1][m * RS + 2 * kq + 1] = l1;
        }
        __nv_bfloat16* bh = reinterpret_cast<__nv_bfloat16*>(sB[buf][0]);
        __nv_bfloat16* bl = reinterpret_cast<__nv_bfloat16*>(sB[buf][1]);
        #pragma unroll
        for (int r = 0; r < B_LD; r++) {
            int v = tid + r * NTHR;
            int k = v / (BN / 4), n4 = v % (BN / 4);
            float4 b4 = *reinterpret_cast<const float4*>(
                W + (size_t)(k0 + k) * ldw + bn + 4 * n4);
            float vals[4] = {b4.x, b4.y, b4.z, b4.w};
            #pragma unroll
            for (int j = 0; j < 4; j++) {
                int n = 4 * n4 + j;
                __nv_bfloat16 h = __float2bfloat16(vals[j]);
                float res = vals[j] - __bfloat162float(h);
                bh[n * (2 * RS) + k] = h;
                bl[n * (2 * RS) + k] = __float2bfloat16(res);
            }
        }
    };

    load_tile(0, 0);
    __syncthreads();

    int buf = 0;
    for (int k0 = 0; k0 < K; k0 += 16) {
        if (k0 + 16 < K) load_tile(k0 + 16, buf ^ 1);

        uint32_t ah[WMT][4], al[WMT][4], bhf[WNT][2], blf[WNT][2];
        #pragma unroll
        for (int im = 0; im < WMT; im++) {
            int r0 = m_off + im * 16 + (l >> 2);
            int c  = l & 3;
            ah[im][0] = sA[buf][0][r0 * RS + c];
            ah[im][1] = sA[buf][0][(r0 + 8) * RS + c];
            ah[im][2] = sA[buf][0][r0 * RS + c + 4];
            ah[im][3] = sA[buf][0][(r0 + 8) * RS + c + 4];
            al[im][0] = sA[buf][1][r0 * RS + c];
            al[im][1] = sA[buf][1][(r0 + 8) * RS + c];
            al[im][2] = sA[buf][1][r0 * RS + c + 4];
            al[im][3] = sA[buf][1][(r0 + 8) * RS + c + 4];
        }
        #pragma unroll
        for (int in = 0; in < WNT; in++) {
            int n0 = n_off + in * 8 + (l >> 2);
            int c  = l & 3;
            bhf[in][0] = sB[buf][0][n0 * RS + c];
            bhf[in][1] = sB[buf][0][n0 * RS + c + 4];
            blf[in][0] = sB[buf][1][n0 * RS + c];
            blf[in][1] = sB[buf][1][n0 * RS + c + 4];
        }
        #pragma unroll
        for (int im = 0; im < WMT; im++)
            #pragma unroll
            for (int in = 0; in < WNT; in++) {
                mma16816(acc[im][in], ah[im], bhf[in]);
                mma16816(acc[im][in], al[im], bhf[in]);
                mma16816(acc[im][in], ah[im], blf[in]);
            }
        __syncthreads();
        buf ^= 1;
    }

    // ---- epilogue ----
    #pragma unroll
    for (int im = 0; im < WMT; im++) {
        int r0 = bm + m_off + im * 16 + (l >> 2);
        #pragma unroll
        for (int in = 0; in < WNT; in++) {
            int n = bn + n_off + in * 8 + 2 * (l & 3);
            float b0 = bias ? __ldg(bias + n)     : 0.f;
            float b1 = bias ? __ldg(bias + n + 1) : 0.f;
            float v0 = acc[im][in][0] + b0;
            float v1 = acc[im][in][1] + b1;
            float v2 = acc[im][in][2] + b0;
            float v3 = acc[im][in][3] + b1;
            size_t i00 = (size_t)r0 * N + n;
            size_t i10 = (size_t)(r0 + 8) * N + n;
            if (epi == 0) {
                C0[i00] = v0; C0[i00 + 1] = v1;
                C0[i10] = v2; C0[i10 + 1] = v3;
            } else {
                dt_epilogue(v0, i00,     C0, C1, aux);
                dt_epilogue(v1, i00 + 1, C0, C1, aux);
                dt_epilogue(v2, i10,     C0, C1, aux);
                dt_epilogue(v3, i10 + 1, C0, C1, aux);
            }
        }
    }
}

// =====================================================================
// Chunked SSM scan (unchanged from R2)
// =====================================================================
__device__ __forceinline__ float pow_dA(float pv, bool exact, int ai, float af)
{
    if (exact) {
        float pw = pv;
        float r = (ai & 1) ? pw : 1.f;
        pw *= pw; if (ai & 2)  r *= pw;
        pw *= pw; if (ai & 4)  r *= pw;
        pw *= pw; if (ai & 8)  r *= pw;
        pw *= pw; if (ai & 16) r *= pw;
        pw *= pw; if (ai & 32) r *= pw;
        return r;
    }
    return __powf(pv, af);
}

__global__ __launch_bounds__(256)
void scan_passA(const float* __restrict__ p,
                const float* __restrict__ du,
                const float* __restrict__ dbc,
                const float* __restrict__ A_log,
                float* __restrict__ afin,
                float* __restrict__ hfin)
{
    int t = blockIdx.x * blockDim.x + threadIdx.x;
    int n = t & 15;
    int d = (t >> 4) & (Dc - 1);
    int ch = (t >> 13) & (NCH - 1);
    int b = t >> 17;

    float af = __expf(__ldg(A_log + d * Nc + n));
    int ai = (int)rintf(af);
    bool exact = (fabsf(af - (float)ai) < 1e-4f * af) && (ai >= 1) && (ai <= 32);

    float aprod = 1.f, h = 0.f;
    int base  = (b * Sc + ch * CL) * Dc + d;
    int bbase = (b * Sc + ch * CL) * 64;
    #pragma unroll 4
    for (int s = 0; s < CL; ++s) {
        float pv  = __ldg(p + base);
        float duv = __ldg(du + base);
        float Bv  = __ldg(dbc + bbase + DTR + n);
        float dA  = pow_dA(pv, exact, ai, af);
        aprod *= dA;
        h = fmaf(dA, h, duv * Bv);
        base += Dc; bbase += 64;
    }
    afin[t] = aprod;
    hfin[t] = h;
}

__global__ __launch_bounds__(256)
void scan_mid(const float* __restrict__ afin,
              const float* __restrict__ hfin,
              float* __restrict__ h0)
{
    int t = blockIdx.x * blockDim.x + threadIdx.x;
    int dn = t & (Dc * 16 - 1);
    int b  = t >> 13;
    float run = 0.f;
    #pragma unroll
    for (int ch = 0; ch < NCH; ++ch) {
        int tt = ((b * NCH + ch) * Dc * 16) + dn;
        h0[tt] = run;
        run = fmaf(__ldg(afin + tt), run, __ldg(hfin + tt));
    }
}

__global__ __launch_bounds__(256)
void scan_passB(const float* __restrict__ p,
                const float* __restrict__ du,
                const float* __restrict__ dbc,
                const float* __restrict__ h0,
                const float* __restrict__ u,
                const float* __restrict__ z1,
                const float* __restrict__ x,
                const float* __restrict__ A_log,
                const float* __restrict__ D_ssm,
                float* __restrict__ out)
{
    int t = blockIdx.x * blockDim.x + threadIdx.x;
    int n = t & 15;
    int d = (t >> 4) & (Dc - 1);
    int ch = (t >> 13) & (NCH - 1);
    int b = t >> 17;

    float af = __expf(__ldg(A_log + d * Nc + n));
    int ai = (int)rintf(af);
    bool exact = (fabsf(af - (float)ai) < 1e-4f * af) && (ai >= 1) && (ai <= 32);
    float Dd = __ldg(D_ssm + d);

    float h = h0[t];
    int base  = (b * Sc + ch * CL) * Dc + d;
    int bbase = (b * Sc + ch * CL) * 64;
    #pragma unroll 2
    for (int s = 0; s < CL; ++s) {
        float pv  = __ldg(p + base);
        float duv = __ldg(du + base);
        float Bv  = __ldg(dbc + bbase + DTR + n);
        float Cv  = __ldg(dbc + bbase + DTR + Nc + n);
        float dA  = pow_dA(pv, exact, ai, af);
        h = fmaf(dA, h, duv * Bv);
        float part = h * Cv;
        part += __shfl_xor_sync(0xffffffffu, part, 8, 16);
        part += __shfl_xor_sync(0xffffffffu, part, 4, 16);
        part += __shfl_xor_sync(0xffffffffu, part, 2, 16);
        part += __shfl_xor_sync(0xffffffffu, part, 1, 16);
        if (n == 0) {
            float uv  = __ldg(u + base);
            float zv  = __ldg(z1 + base);
            float xv  = __ldg(x + base);
            float x2v = part + Dd * uv;
            float sil = zv / (1.f + __expf(-zv));
            out[base] = (zv + x2v) * sil + xv;
        }
        base += Dc; bbase += 64;
    }
}

// =====================================================================
// launch
// =====================================================================
extern "C" void kernel_launch(void* const* d_in, const int* in_sizes, int n_in,
                              void* d_out, int out_size)
{
    const float* x      = (const float*)d_in[0];
    const float* gamma  = (const float*)d_in[1];
    const float* beta   = (const float*)d_in[2];
    const float* W_proj = (const float*)d_in[3];
    const float* b_proj = (const float*)d_in[4];
    // d_in[5] W_fwd, d_in[6] b_fwd: dead code (x1_ssm unused in reference)
    const float* W_bwd  = (const float*)d_in[7];
    const float* b_bwd  = (const float*)d_in[8];
    const float* W_dbc  = (const float*)d_in[9];
    const float* W_dt   = (const float*)d_in[10];
    const float* b_dt   = (const float*)d_in[11];
    const float* A_log  = (const float*)d_in[12];
    const float* D_ssm  = (const float*)d_in[13];
    float* out = (float*)d_out;

    static float *p_xn = nullptr, *p_z1, *p_bwd, *p_dbc, *p_p, *p_du,
                 *p_afin, *p_hfin, *p_h0;
    if (!p_xn) {
        void* v;
        cudaGetSymbolAddress(&v, g_xn);   p_xn   = (float*)v;
        cudaGetSymbolAddress(&v, g_z1);   p_z1   = (float*)v;
        cudaGetSymbolAddress(&v, g_bwd);  p_bwd  = (float*)v;
        cudaGetSymbolAddress(&v, g_dbc);  p_dbc  = (float*)v;
        cudaGetSymbolAddress(&v, g_p);    p_p    = (float*)v;
        cudaGetSymbolAddress(&v, g_du);   p_du   = (float*)v;
        cudaGetSymbolAddress(&v, g_afin); p_afin = (float*)v;
        cudaGetSymbolAddress(&v, g_hfin); p_hfin = (float*)v;
        cudaGetSymbolAddress(&v, g_h0);   p_h0   = (float*)v;
    }

    // 1) LayerNorm
    ln_kernel<<<BS, 128>>>(x, gamma, beta, p_xn);

    // 2) z1 = xn @ W_proj + b_proj   (8192 x 512 x 512)
    {
        dim3 g(Dc / 128, BS / 128);
        mma_gemm<128,128,4,4,256><<<g, 256>>>(p_xn, Dc, W_proj, Dc, b_proj,
                                              p_z1, nullptr, nullptr,
                                              BS, Dc, Dc, 0);
    }
    // 3) bwd = z1 @ W_bwd + b_bwd
    {
        dim3 g(Dc / 128, BS / 128);
        mma_gemm<128,128,4,4,256><<<g, 256>>>(p_z1, Dc, W_bwd, Dc, b_bwd,
                                              p_bwd, nullptr, nullptr,
                                              BS, Dc, Dc, 0);
    }
    // 4) dbc = bwd @ W_dbc           (8192 x 64 x 512)
    {
        dim3 g(1, BS / 64);
        mma_gemm<64,64,2,4,128><<<g, 128>>>(p_bwd, Dc, W_dbc, 64, nullptr,
                                            p_dbc, nullptr, nullptr,
                                            BS, 64, Dc, 0);
    }
    // 5) delta GEMM + fused softplus/exp epilogue -> p, du  (K=32)
    {
        dim3 g(Dc / 128, BS / 128);
        mma_gemm<128,128,4,4,256><<<g, 256>>>(p_dbc, 64, W_dt, Dc, b_dt,
                                              p_p, p_du, p_bwd,
                                              BS, Dc, DTR, 1);
    }

    // 6) chunk-parallel SSM scan + fused final elementwise
    scan_passA<<<NSCAN / 256, 256>>>(p_p, p_du, p_dbc, A_log, p_afin, p_hfin);
    scan_mid<<<(Bc * Dc * Nc) / 256, 256>>>(p_afin, p_hfin, p_h0);
    scan_passB<<<NSCAN / 256, 256>>>(p_p, p_du, p_dbc, p_h0,
                                     p_bwd, p_z1, x, A_log, D_ssm, out);
}